// round 1
// baseline (speedup 1.0000x reference)
#include <cuda_runtime.h>

#define N_ATOMS 1024
#define NIMG 27
#define PAIRS_PER_BLOCK 256
#define CUT2_MARGIN 25.05f

// Cartesian image offsets: offc[k] = offsets[k] @ cell  (27 x 3, padded to float4)
__device__ float4 g_offc[NIMG];

__global__ void offc_kernel(const float* __restrict__ cell) {
    int k = threadIdx.x;
    if (k < NIMG) {
        // meshgrid(g,g,g,indexing="ij") -> k = a*9 + b*3 + c, g = {-1,0,1}
        float o0 = (float)(k / 9) - 1.0f;
        float o1 = (float)((k / 3) % 3) - 1.0f;
        float o2 = (float)(k % 3) - 1.0f;
        float4 r;
        r.x = fmaf(o2, cell[6], fmaf(o1, cell[3], o0 * cell[0]));
        r.y = fmaf(o2, cell[7], fmaf(o1, cell[4], o0 * cell[1]));
        r.z = fmaf(o2, cell[8], fmaf(o1, cell[5], o0 * cell[2]));
        r.w = 0.0f;
        g_offc[k] = r;
    }
}

__global__ __launch_bounds__(PAIRS_PER_BLOCK)
void prg_kernel(const float* __restrict__ frac,
                const float* __restrict__ cell,
                float* __restrict__ out) {
    __shared__ float4 s_offc[NIMG];
    __shared__ __align__(16) float s_buf[PAIRS_PER_BLOCK * NIMG];

    const int tid = threadIdx.x;
    if (tid < NIMG) s_offc[tid] = g_offc[tid];

    // cell is 9 floats, uniform across the grid: L1-broadcast loads into regs
    const float c00 = cell[0], c01 = cell[1], c02 = cell[2];
    const float c10 = cell[3], c11 = cell[4], c12 = cell[5];
    const float c20 = cell[6], c21 = cell[7], c22 = cell[8];

    const int pair = blockIdx.x * PAIRS_PER_BLOCK + tid;
    const int i = pair >> 10;
    const int j = pair & 1023;

    const float fi0 = frac[i * 3 + 0], fi1 = frac[i * 3 + 1], fi2 = frac[i * 3 + 2];
    const float fj0 = frac[j * 3 + 0], fj1 = frac[j * 3 + 1], fj2 = frac[j * 3 + 2];

    // t = frac[j] - frac[i]  (matches reference: sub first, offset added later)
    const float t0 = fj0 - fi0, t1 = fj1 - fi1, t2 = fj2 - fi2;

    // Fast-path base: b = t @ cell (hoisted out of the 27-image loop)
    const float bx = fmaf(t2, c20, fmaf(t1, c10, t0 * c00));
    const float by = fmaf(t2, c21, fmaf(t1, c11, t0 * c01));
    const float bz = fmaf(t2, c22, fmaf(t1, c12, t0 * c02));

    __syncthreads();

    float* my = &s_buf[tid * NIMG];  // stride 27 vs 32 banks: conflict-free

    #pragma unroll
    for (int k = 0; k < NIMG; k++) {
        const float4 oc = s_offc[k];
        const float vx = bx + oc.x;
        const float vy = by + oc.y;
        const float vz = bz + oc.z;
        const float d2f = fmaf(vz, vz, fmaf(vy, vy, vx * vx));

        float r = 0.0f;
        if (d2f < CUT2_MARGIN) {
            // Exact path in reference op order: dfrac = (fj - fi) + off, then @ cell.
            // k is a compile-time constant here (loop fully unrolled).
            const float o0 = (float)(k / 9) - 1.0f;
            const float o1 = (float)((k / 3) % 3) - 1.0f;
            const float o2 = (float)(k % 3) - 1.0f;
            const float d0 = t0 + o0, d1 = t1 + o1, d2 = t2 + o2;
            const float wx = fmaf(d2, c20, fmaf(d1, c10, d0 * c00));
            const float wy = fmaf(d2, c21, fmaf(d1, c11, d0 * c01));
            const float wz = fmaf(d2, c22, fmaf(d1, c12, d0 * c02));
            const float e2 = fmaf(wz, wz, fmaf(wy, wy, wx * wx));
            if (e2 > 1e-12f) {
                const float dist = __fsqrt_rn(e2);
                if (dist < 5.0f) r = dist;
            }
        }
        my[k] = r;
    }

    __syncthreads();

    // Coalesced float4 writeback: block owns out[blk*6912 .. blk*6912+6912)
    const float4* src = (const float4*)s_buf;
    float4* dst = (float4*)(out + (size_t)blockIdx.x * (PAIRS_PER_BLOCK * NIMG));
    for (int idx = tid; idx < PAIRS_PER_BLOCK * NIMG / 4; idx += PAIRS_PER_BLOCK) {
        dst[idx] = src[idx];
    }
}

extern "C" void kernel_launch(void* const* d_in, const int* in_sizes, int n_in,
                              void* d_out, int out_size) {
    const float* frac = (const float*)d_in[0];  // [1024, 3]
    const float* cell = (const float*)d_in[1];  // [3, 3]
    float* out = (float*)d_out;                 // [1024, 1024, 27]

    offc_kernel<<<1, 32>>>(cell);
    const int n_pairs = N_ATOMS * N_ATOMS;
    prg_kernel<<<n_pairs / PAIRS_PER_BLOCK, PAIRS_PER_BLOCK>>>(frac, cell, out);
}

// round 2
// speedup vs baseline: 1.0805x; 1.0805x over previous
#include <cuda_runtime.h>
#include <cstdint>

#define N_ATOMS 1024
#define NIMG 27
#define PAIRS_PER_BLOCK 256
#define TILE_FLOATS (PAIRS_PER_BLOCK * NIMG)   // 6912 floats = 27648 bytes
#define TILE_BYTES (TILE_FLOATS * 4)
#define CUT2_MARGIN 25.05f

// Cartesian image offsets: offc[k] = offsets[k] @ cell  (27 x 3, padded to float4)
__device__ float4 g_offc[NIMG];

__global__ void offc_kernel(const float* __restrict__ cell) {
    int k = threadIdx.x;
    if (k < NIMG) {
        // meshgrid(g,g,g,indexing="ij") -> k = a*9 + b*3 + c, g = {-1,0,1}
        float o0 = (float)(k / 9) - 1.0f;
        float o1 = (float)((k / 3) % 3) - 1.0f;
        float o2 = (float)(k % 3) - 1.0f;
        float4 r;
        r.x = fmaf(o2, cell[6], fmaf(o1, cell[3], o0 * cell[0]));
        r.y = fmaf(o2, cell[7], fmaf(o1, cell[4], o0 * cell[1]));
        r.z = fmaf(o2, cell[8], fmaf(o1, cell[5], o0 * cell[2]));
        r.w = 0.0f;
        g_offc[k] = r;
    }
}

__global__ __launch_bounds__(PAIRS_PER_BLOCK)
void prg_kernel(const float* __restrict__ frac,
                const float* __restrict__ cell,
                float* __restrict__ out) {
    __shared__ float4 s_offc[NIMG];
    __shared__ __align__(16) float s_buf[TILE_FLOATS];

    const int tid = threadIdx.x;
    if (tid < NIMG) s_offc[tid] = g_offc[tid];

    // cell is 9 floats, uniform across the grid: L1-broadcast loads into regs
    const float c00 = cell[0], c01 = cell[1], c02 = cell[2];
    const float c10 = cell[3], c11 = cell[4], c12 = cell[5];
    const float c20 = cell[6], c21 = cell[7], c22 = cell[8];

    const int pair = blockIdx.x * PAIRS_PER_BLOCK + tid;
    const int i = pair >> 10;
    const int j = pair & 1023;

    const float fi0 = frac[i * 3 + 0], fi1 = frac[i * 3 + 1], fi2 = frac[i * 3 + 2];
    const float fj0 = frac[j * 3 + 0], fj1 = frac[j * 3 + 1], fj2 = frac[j * 3 + 2];

    // t = frac[j] - frac[i]  (matches reference: sub first, offset added later)
    const float t0 = fj0 - fi0, t1 = fj1 - fi1, t2 = fj2 - fi2;

    // Fast-path base: b = t @ cell (hoisted out of the 27-image loop)
    const float bx = fmaf(t2, c20, fmaf(t1, c10, t0 * c00));
    const float by = fmaf(t2, c21, fmaf(t1, c11, t0 * c01));
    const float bz = fmaf(t2, c22, fmaf(t1, c12, t0 * c02));

    __syncthreads();

    float* my = &s_buf[tid * NIMG];  // stride 27 vs 32 banks: conflict-free

    #pragma unroll
    for (int k = 0; k < NIMG; k++) {
        const float4 oc = s_offc[k];
        const float vx = bx + oc.x;
        const float vy = by + oc.y;
        const float vz = bz + oc.z;
        const float d2f = fmaf(vz, vz, fmaf(vy, vy, vx * vx));

        float r = 0.0f;
        if (d2f < CUT2_MARGIN) {
            // Exact path in reference op order: dfrac = (fj - fi) + off, then @ cell.
            // k is a compile-time constant here (loop fully unrolled).
            const float o0 = (float)(k / 9) - 1.0f;
            const float o1 = (float)((k / 3) % 3) - 1.0f;
            const float o2 = (float)(k % 3) - 1.0f;
            const float d0 = t0 + o0, d1 = t1 + o1, d2 = t2 + o2;
            const float wx = fmaf(d2, c20, fmaf(d1, c10, d0 * c00));
            const float wy = fmaf(d2, c21, fmaf(d1, c11, d0 * c01));
            const float wz = fmaf(d2, c22, fmaf(d1, c12, d0 * c02));
            const float e2 = fmaf(wz, wz, fmaf(wy, wy, wx * wx));
            if (e2 > 1e-12f) {
                const float dist = __fsqrt_rn(e2);
                if (dist < 5.0f) r = dist;
            }
        }
        my[k] = r;
    }

    __syncthreads();

    // Bulk TMA store: one engine-driven smem->global copy of the whole tile.
    // Replaces the per-thread LDS.128 + STG.128 loop (removes ~226MB of L1
    // wavefront traffic across the grid).
    if (tid == 0) {
        // Order the generic-proxy STS writes before the async-proxy read.
        asm volatile("fence.proxy.async.shared::cta;" ::: "memory");
        uint32_t saddr;
        asm volatile("{ .reg .u64 t; cvta.to.shared.u64 t, %1; cvt.u32.u64 %0, t; }"
                     : "=r"(saddr) : "l"(s_buf));
        float* dst = out + (size_t)blockIdx.x * TILE_FLOATS;
        asm volatile("cp.async.bulk.global.shared::cta.bulk_group [%0], [%1], %2;"
                     :: "l"(dst), "r"(saddr), "n"(TILE_BYTES) : "memory");
        asm volatile("cp.async.bulk.commit_group;" ::: "memory");
        // Wait for the store to fully commit before this block retires.
        asm volatile("cp.async.bulk.wait_group 0;" ::: "memory");
    }
}

extern "C" void kernel_launch(void* const* d_in, const int* in_sizes, int n_in,
                              void* d_out, int out_size) {
    const float* frac = (const float*)d_in[0];  // [1024, 3]
    const float* cell = (const float*)d_in[1];  // [3, 3]
    float* out = (float*)d_out;                 // [1024, 1024, 27]

    offc_kernel<<<1, 32>>>(cell);
    const int n_pairs = N_ATOMS * N_ATOMS;
    prg_kernel<<<n_pairs / PAIRS_PER_BLOCK, PAIRS_PER_BLOCK>>>(frac, cell, out);
}

// round 3
// speedup vs baseline: 1.1030x; 1.0209x over previous
#include <cuda_runtime.h>
#include <cstdint>

#define N_ATOMS 1024
#define NIMG 27
#define NPK 14                      // packed image-pairs (27 images + 1 dummy)
#define PAIRS_PER_BLOCK 256
#define TILE_FLOATS (PAIRS_PER_BLOCK * NIMG)   // 6912 floats = 27648 bytes
#define TILE_BYTES (TILE_FLOATS * 4)
#define CUT2_MARGIN 25.05f

// Packed Cartesian image offsets: lane0 = image 2m, lane1 = image 2m+1.
// Image 27 is a dummy with a huge offset (never screens positive).
__device__ unsigned long long g_pox[NPK], g_poy[NPK], g_poz[NPK];

__device__ __forceinline__ unsigned long long pk2(float lo, float hi) {
    unsigned long long r;
    asm("mov.b64 %0, {%1, %2};" : "=l"(r) : "f"(lo), "f"(hi));
    return r;
}
__device__ __forceinline__ unsigned long long add2(unsigned long long a, unsigned long long b) {
    unsigned long long r;
    asm("add.rn.f32x2 %0, %1, %2;" : "=l"(r) : "l"(a), "l"(b));
    return r;
}
__device__ __forceinline__ unsigned long long fma2(unsigned long long a, unsigned long long b,
                                                   unsigned long long c) {
    unsigned long long r;
    asm("fma.rn.f32x2 %0, %1, %2, %3;" : "=l"(r) : "l"(a), "l"(b), "l"(c));
    return r;
}

__global__ void offc_kernel(const float* __restrict__ cell) {
    int m = threadIdx.x;
    if (m < NPK) {
        float x[2], y[2], z[2];
        #pragma unroll
        for (int h = 0; h < 2; h++) {
            int k = 2 * m + h;
            if (k < NIMG) {
                float o0 = (float)(k / 9) - 1.0f;
                float o1 = (float)((k / 3) % 3) - 1.0f;
                float o2 = (float)(k % 3) - 1.0f;
                x[h] = fmaf(o2, cell[6], fmaf(o1, cell[3], o0 * cell[0]));
                y[h] = fmaf(o2, cell[7], fmaf(o1, cell[4], o0 * cell[1]));
                z[h] = fmaf(o2, cell[8], fmaf(o1, cell[5], o0 * cell[2]));
            } else {
                x[h] = 1.0e6f; y[h] = 1.0e6f; z[h] = 1.0e6f;  // dummy: d2 huge
            }
        }
        g_pox[m] = pk2(x[0], x[1]);
        g_poy[m] = pk2(y[0], y[1]);
        g_poz[m] = pk2(z[0], z[1]);
    }
}

__global__ __launch_bounds__(PAIRS_PER_BLOCK)
void prg_kernel(const float* __restrict__ frac,
                const float* __restrict__ cell,
                float* __restrict__ out) {
    __shared__ unsigned long long s_pox[NPK], s_poy[NPK], s_poz[NPK];
    __shared__ __align__(16) float s_buf[TILE_FLOATS];

    const int tid = threadIdx.x;
    if (tid < NPK) {
        s_pox[tid] = g_pox[tid];
        s_poy[tid] = g_poy[tid];
        s_poz[tid] = g_poz[tid];
    }

    // Pre-zero the tile: 1728 float4 across 256 threads (7 iters, last partial).
    {
        float4* z4 = (float4*)s_buf;
        const float4 z = make_float4(0.f, 0.f, 0.f, 0.f);
        #pragma unroll
        for (int q = 0; q < 7; q++) {
            int idx = tid + q * PAIRS_PER_BLOCK;
            if (idx < TILE_FLOATS / 4) z4[idx] = z;
        }
    }

    const float c00 = cell[0], c01 = cell[1], c02 = cell[2];
    const float c10 = cell[3], c11 = cell[4], c12 = cell[5];
    const float c20 = cell[6], c21 = cell[7], c22 = cell[8];

    const int pair = blockIdx.x * PAIRS_PER_BLOCK + tid;
    const int i = pair >> 10;
    const int j = pair & 1023;

    const float fi0 = frac[i * 3 + 0], fi1 = frac[i * 3 + 1], fi2 = frac[i * 3 + 2];
    const float fj0 = frac[j * 3 + 0], fj1 = frac[j * 3 + 1], fj2 = frac[j * 3 + 2];

    // t = frac[j] - frac[i]  (reference order: sub first, offset added later)
    const float t0 = fj0 - fi0, t1 = fj1 - fi1, t2 = fj2 - fi2;

    // Fast-path base b = t @ cell, replicated into both packed lanes
    const float bx = fmaf(t2, c20, fmaf(t1, c10, t0 * c00));
    const float by = fmaf(t2, c21, fmaf(t1, c11, t0 * c01));
    const float bz = fmaf(t2, c22, fmaf(t1, c12, t0 * c02));
    const unsigned long long bx2 = pk2(bx, bx);
    const unsigned long long by2 = pk2(by, by);
    const unsigned long long bz2 = pk2(bz, bz);
    const unsigned long long negt2 = pk2(-CUT2_MARGIN, -CUT2_MARGIN);

    __syncthreads();  // covers s_po* load + pre-zero (loop writes only own hits)

    float* my = &s_buf[tid * NIMG];

    #pragma unroll
    for (int m = 0; m < NPK; m++) {
        const unsigned long long vx = add2(bx2, s_pox[m]);
        const unsigned long long vy = add2(by2, s_poy[m]);
        const unsigned long long vz = add2(bz2, s_poz[m]);
        // acc = v.v - 25.05 (per lane); hit <=> sign bit set
        unsigned long long acc = fma2(vx, vx, negt2);
        acc = fma2(vy, vy, acc);
        acc = fma2(vz, vz, acc);
        unsigned int lo, hi;
        asm("mov.b64 {%0, %1}, %2;" : "=r"(lo), "=r"(hi) : "l"(acc));
        if ((int)(lo | hi) < 0) {
            // Rare: at least one of images (2m, 2m+1) may be an edge.
            // Recompute both in exact reference op order; store only real hits.
            #pragma unroll
            for (int h = 0; h < 2; h++) {
                const int k = 2 * m + h;
                if (k < NIMG) {
                    const float o0 = (float)(k / 9) - 1.0f;
                    const float o1 = (float)((k / 3) % 3) - 1.0f;
                    const float o2 = (float)(k % 3) - 1.0f;
                    const float d0 = t0 + o0, d1 = t1 + o1, d2 = t2 + o2;
                    const float wx = fmaf(d2, c20, fmaf(d1, c10, d0 * c00));
                    const float wy = fmaf(d2, c21, fmaf(d1, c11, d0 * c01));
                    const float wz = fmaf(d2, c22, fmaf(d1, c12, d0 * c02));
                    const float e2 = fmaf(wz, wz, fmaf(wy, wy, wx * wx));
                    if (e2 > 1e-12f) {
                        const float dist = __fsqrt_rn(e2);
                        if (dist < 5.0f) my[k] = dist;
                    }
                }
            }
        }
    }

    __syncthreads();

    // Bulk TMA store: one engine-driven smem->global copy of the whole tile.
    if (tid == 0) {
        asm volatile("fence.proxy.async.shared::cta;" ::: "memory");
        uint32_t saddr;
        asm volatile("{ .reg .u64 t; cvta.to.shared.u64 t, %1; cvt.u32.u64 %0, t; }"
                     : "=r"(saddr) : "l"(s_buf));
        float* dst = out + (size_t)blockIdx.x * TILE_FLOATS;
        asm volatile("cp.async.bulk.global.shared::cta.bulk_group [%0], [%1], %2;"
                     :: "l"(dst), "r"(saddr), "n"(TILE_BYTES) : "memory");
        asm volatile("cp.async.bulk.commit_group;" ::: "memory");
        asm volatile("cp.async.bulk.wait_group 0;" ::: "memory");
    }
}

extern "C" void kernel_launch(void* const* d_in, const int* in_sizes, int n_in,
                              void* d_out, int out_size) {
    const float* frac = (const float*)d_in[0];  // [1024, 3]
    const float* cell = (const float*)d_in[1];  // [3, 3]
    float* out = (float*)d_out;                 // [1024, 1024, 27]

    offc_kernel<<<1, 32>>>(cell);
    const int n_pairs = N_ATOMS * N_ATOMS;
    prg_kernel<<<n_pairs / PAIRS_PER_BLOCK, PAIRS_PER_BLOCK>>>(frac, cell, out);
}